// round 8
// baseline (speedup 1.0000x reference)
#include <cuda_runtime.h>

#define NJ   32
#define TPB  64
#define EPB  (TPB / 2)     // 32 elements per block, 2 threads each
#define OUTC 94

// ---- dynamic smem float offsets ----
#define S_OUT   0                       // EPB*OUTC = 3008 floats (also cfg-stage scratch)
#define S_BASE  (EPB * OUTC)            // 3008  (EPB x 7)
#define S_TGT   (S_BASE + EPB * 7)      // 3232  (4 x 7)
#define S_DB    (S_TGT + 28)            // (7)
#define S_REST  (S_DB + 7)              // (32)
#define S_JLO   (S_REST + 32)           // (32)
#define S_JUP   (S_JLO + 32)            // (32)
#define S_JOFF  (S_JUP + 32)            // (32 x 7)
#define S_P     (S_JOFF + 224)          // (32 x 4)
#define S_TOTAL (S_P + 128)             // 3715 floats = 14860 B

#define CFG_PAD 36                      // padded cfg row stride in the staging scratch

struct Q { float x, y, z, w; };
struct V { float x, y, z; };

__device__ __forceinline__ V vcross(V a, V b) {
    return {a.y * b.z - a.z * b.y,
            a.z * b.x - a.x * b.z,
            a.x * b.y - a.y * b.x};
}

__device__ __forceinline__ V qrot(Q q, V t) {
    V v{q.x, q.y, q.z};
    V u = vcross(v, t);
    u.x = fmaf(q.w, t.x, u.x);
    u.y = fmaf(q.w, t.y, u.y);
    u.z = fmaf(q.w, t.z, u.z);
    V c = vcross(v, u);
    return {fmaf(2.0f, c.x, t.x), fmaf(2.0f, c.y, t.y), fmaf(2.0f, c.z, t.z)};
}

__device__ __forceinline__ Q qmul(Q a, Q b) {
    Q r;
    r.w = a.w * b.w - a.x * b.x - a.y * b.y - a.z * b.z;
    r.x = a.w * b.x + b.w * a.x + a.y * b.z - a.z * b.y;
    r.y = a.w * b.y + b.w * a.y + a.z * b.x - a.x * b.z;
    r.z = a.w * b.z + b.w * a.z + a.x * b.y - a.y * b.x;
    return r;
}

// (t1,q1) <- (t1,q1) o (t2,q2)
__device__ __forceinline__ void se3_acc(V& t1, Q& q1, V t2, Q q2) {
    V r = qrot(q1, t2);
    t1.x += r.x; t1.y += r.y; t1.z += r.z;
    q1 = qmul(q1, q2);
}

// out = (t1,q1) o (t2,q2), non-destructive
__device__ __forceinline__ void se3_comp(V t1, Q q1, V t2, Q q2, V& to, Q& qo) {
    V r = qrot(q1, t2);
    to.x = t1.x + r.x; to.y = t1.y + r.y; to.z = t1.z + r.z;
    qo = qmul(q1, q2);
}

// atan2(y,x), y >= 0, x >= 0, not both zero
__device__ __forceinline__ float atan2pos(float y, float x) {
    float mn = fminf(y, x), mx = fmaxf(y, x);
    float r  = __fdividef(mn, mx);
    float r2 = r * r;
    float p = fmaf(r2, -0.0117212f,  0.05265332f);
    p = fmaf(r2, p, -0.11643287f);
    p = fmaf(r2, p,  0.19354346f);
    p = fmaf(r2, p, -0.33262347f);
    p = fmaf(r2, p,  0.99997726f);
    float th = r * p;
    return (y > x) ? (1.57079632679489662f - th) : th;
}

// se3_log for unit quaternion (trig-free tail)
__device__ __forceinline__ void se3_log(V t, Q q, V& rho, V& phi) {
    float sgn = (q.w < 0.0f) ? -1.0f : 1.0f;
    float qx = q.x * sgn, qy = q.y * sgn, qz = q.z * sgn, qw = q.w * sgn;
    float nv2 = qx * qx + qy * qy + qz * qz;
    float nv  = sqrtf(fmaxf(nv2, 1e-14f));
    float angle = 2.0f * atan2pos(nv, qw);
    float wsafe = (fabsf(qw) > 1e-8f) ? qw : 1.0f;
    float scale = (nv < 1e-6f) ? __fdividef(2.0f, wsafe) : __fdividef(angle, nv);
    phi = {qx * scale, qy * scale, qz * scale};

    float th2 = angle * angle;
    float abig = __fdividef(1.0f - 0.5f * scale * qw, th2);
    float a = (angle < 1e-4f) ? (1.0f / 12.0f + th2 * (1.0f / 720.0f)) : abig;

    V pt  = vcross(phi, t);
    V ppt = vcross(phi, pt);
    rho = {t.x - 0.5f * pt.x + a * ppt.x,
           t.y - 0.5f * pt.y + a * ppt.y,
           t.z - 0.5f * pt.z + a * ppt.z};
}

__device__ __forceinline__ void pose_err_log(const float* tp, V at, Q aq,
                                             V& rho, V& phi) {
    Q qi{-tp[3], -tp[4], -tp[5], tp[6]};
    V d{at.x - tp[0], at.y - tp[1], at.z - tp[2]};
    V pe = qrot(qi, d);
    Q qe = qmul(qi, aq);
    se3_log(pe, qe, rho, phi);
}

// product of X_{j0} .. X_{j0+7} via pairwise tree (th8 = angles for those joints)
__device__ __forceinline__ void prod8(const float* s, int j0, const float* th8,
                                      V& St, Q& Sq) {
    Q M[8];
    #pragma unroll
    for (int i = 0; i < 8; i++) {
        float sh, ch;
        __sincosf(0.5f * th8[i], &sh, &ch);
        const float* o = s + S_JOFF + (j0 + i) * 7;
        const float* p = s + S_P + (j0 + i) * 4;
        M[i].x = fmaf(sh, p[0], ch * o[3]);
        M[i].y = fmaf(sh, p[1], ch * o[4]);
        M[i].z = fmaf(sh, p[2], ch * o[5]);
        M[i].w = fmaf(sh, p[3], ch * o[6]);
    }
    const float* o0 = s + S_JOFF + (j0 + 0) * 7;
    const float* o1 = s + S_JOFF + (j0 + 1) * 7;
    const float* o2 = s + S_JOFF + (j0 + 2) * 7;
    const float* o3 = s + S_JOFF + (j0 + 3) * 7;
    const float* o4 = s + S_JOFF + (j0 + 4) * 7;
    const float* o5 = s + S_JOFF + (j0 + 5) * 7;
    const float* o6 = s + S_JOFF + (j0 + 6) * 7;
    const float* o7 = s + S_JOFF + (j0 + 7) * 7;

    V t01{o0[0], o0[1], o0[2]}; Q q01 = M[0];
    se3_acc(t01, q01, V{o1[0], o1[1], o1[2]}, M[1]);
    V t23{o2[0], o2[1], o2[2]}; Q q23 = M[2];
    se3_acc(t23, q23, V{o3[0], o3[1], o3[2]}, M[3]);
    V t45{o4[0], o4[1], o4[2]}; Q q45 = M[4];
    se3_acc(t45, q45, V{o5[0], o5[1], o5[2]}, M[5]);
    V t67{o6[0], o6[1], o6[2]}; Q q67 = M[6];
    se3_acc(t67, q67, V{o7[0], o7[1], o7[2]}, M[7]);

    se3_acc(t01, q01, t23, q23);
    se3_acc(t45, q45, t67, q67);
    se3_acc(t01, q01, t45, q45);
    St = t01; Sq = q01;
}

__global__ void __launch_bounds__(TPB, 8)
ik_residual_kernel(const float* __restrict__ cfg,
                   const float* __restrict__ base,
                   const float* __restrict__ tgt,
                   const float* __restrict__ dbase,
                   const float* __restrict__ rest,
                   const float* __restrict__ joff,
                   const float* __restrict__ jaxis,
                   const float* __restrict__ jlo,
                   const float* __restrict__ jup,
                   float* __restrict__ out) {
    extern __shared__ float s[];

    const int t    = threadIdx.x;
    const int elem = t >> 1;        // 0..31
    const int seg  = t & 1;         // 0 -> joints 0-15, 1 -> joints 16-31
    const int e0   = blockIdx.x * EPB;

    // ---- stage constants + base poses + cfg tile (cfg -> S_OUT scratch) ----
    {
        const float* gb = base + (size_t)e0 * 7;
        #pragma unroll
        for (int i = t; i < EPB * 7; i += TPB) s[S_BASE + i] = gb[i];

        const float4* gc = (const float4*)(cfg + (size_t)e0 * NJ);
        #pragma unroll
        for (int f = t; f < EPB * (NJ / 4); f += TPB) {
            int r = f >> 3;
            int c = f & 7;
            *(float4*)(s + S_OUT + r * CFG_PAD + c * 4) = __ldg(gc + f);
        }

        #pragma unroll
        for (int i = t; i < 224; i += TPB) s[S_JOFF + i] = __ldg(joff + i);
        if (t < 28) s[S_TGT + t] = __ldg(tgt + t);
        if (t < 7)  s[S_DB + t]  = __ldg(dbase + t);
        if (t < 32) {
            s[S_REST + t] = __ldg(rest + t);
            s[S_JLO + t]  = __ldg(jlo + t);
            s[S_JUP + t]  = __ldg(jup + t);
            float ox = __ldg(joff + t * 7 + 3), oy = __ldg(joff + t * 7 + 4);
            float oz = __ldg(joff + t * 7 + 5), ow = __ldg(joff + t * 7 + 6);
            float ax = __ldg(jaxis + t * 3 + 0), ay = __ldg(jaxis + t * 3 + 1);
            float az = __ldg(jaxis + t * 3 + 2);
            s[S_P + t * 4 + 0] = ow * ax + oy * az - oz * ay;
            s[S_P + t * 4 + 1] = ow * ay + oz * ax - ox * az;
            s[S_P + t * 4 + 2] = ow * az + ox * ay - oy * ax;
            s[S_P + t * 4 + 3] = -(ox * ax + oy * ay + oz * az);
        }
    }
    __syncthreads();

    // own half of the cfg row (16 angles) + base pose
    const int j0 = seg * 16;
    float th[16];
    {
        const float4* cr = (const float4*)(s + S_OUT + elem * CFG_PAD + seg * 16);
        #pragma unroll
        for (int i = 0; i < 4; i++) {
            float4 v = cr[i];
            th[4*i+0] = v.x; th[4*i+1] = v.y; th[4*i+2] = v.z; th[4*i+3] = v.w;
        }
    }
    float bp[7];
    #pragma unroll
    for (int i = 0; i < 7; i++) bp[i] = s[S_BASE + elem * 7 + i];
    __syncthreads();   // cfg scratch becomes output staging

    float* row = s + S_OUT + elem * OUTC;

    // ---- limit / rest residuals for this thread's 16 joints ----
    #pragma unroll
    for (int i = 0; i < 16; i++) {
        const int j = j0 + i;
        float lim = fmaxf(th[i] - s[S_JUP + j], 0.0f)
                  + fminf(th[i] - s[S_JLO + j], 0.0f);
        row[24 + j] = lim * 10.0f;
        row[56 + j] = (th[i] - s[S_REST + j]) * 0.1f;
    }

    // ---- two 8-joint products + 16-joint product ----
    V S1t, S2t, Et; Q S1q, S2q, Eq;
    prod8(s, j0,     th,     S1t, S1q);
    prod8(s, j0 + 8, th + 8, S2t, S2q);
    se3_comp(S1t, S1q, S2t, S2q, Et, Eq);      // E = S1 o S2 (16 joints)

    // ---- G = base o E (lane0: pose at link 16; lane1: discarded) ----
    V bt{bp[0], bp[1], bp[2]};
    Q bq{bp[3], bp[4], bp[5], bp[6]};
    V Gt; Q Gq;
    se3_comp(bt, bq, Et, Eq, Gt, Gq);

    // ---- broadcast lane0's G (=T16) to the pair ----
    V Lt; Q Lq;
    Lt.x = __shfl_sync(0xffffffffu, Gt.x, 0, 2);
    Lt.y = __shfl_sync(0xffffffffu, Gt.y, 0, 2);
    Lt.z = __shfl_sync(0xffffffffu, Gt.z, 0, 2);
    Lq.x = __shfl_sync(0xffffffffu, Gq.x, 0, 2);
    Lq.y = __shfl_sync(0xffffffffu, Gq.y, 0, 2);
    Lq.z = __shfl_sync(0xffffffffu, Gq.z, 0, 2);
    Lq.w = __shfl_sync(0xffffffffu, Gq.w, 0, 2);

    // ---- uniform prefix select: seg0 -> base, seg1 -> T16 ----
    V Pt; Q Pq;
    Pt.x = seg ? Lt.x : bt.x;  Pt.y = seg ? Lt.y : bt.y;  Pt.z = seg ? Lt.z : bt.z;
    Pq.x = seg ? Lq.x : bq.x;  Pq.y = seg ? Lq.y : bq.y;
    Pq.z = seg ? Lq.z : bq.z;  Pq.w = seg ? Lq.w : bq.w;

    // U1 = P o S1  (lane0: T8,  lane1: T24)
    // U2 = P o E   (lane0: T16, lane1: T32)    -- independent composes
    V U1t, U2t; Q U1q, U2q;
    se3_comp(Pt, Pq, S1t, S1q, U1t, U1q);
    se3_comp(Pt, Pq, Et,  Eq,  U2t, U2q);

    // ---- pose residuals (2 per thread, uniform code) ----
    {
        V rho, phi;
        int k = seg * 2;
        pose_err_log(s + S_TGT + k * 7, U1t, U1q, rho, phi);
        row[k * 6 + 0] = rho.x;
        row[k * 6 + 1] = rho.y;
        row[k * 6 + 2] = rho.z;
        row[k * 6 + 3] = 0.5f * phi.x;
        row[k * 6 + 4] = 0.5f * phi.y;
        row[k * 6 + 5] = 0.5f * phi.z;

        k = seg * 2 + 1;
        pose_err_log(s + S_TGT + k * 7, U2t, U2q, rho, phi);
        row[k * 6 + 0] = rho.x;
        row[k * 6 + 1] = rho.y;
        row[k * 6 + 2] = rho.z;
        row[k * 6 + 3] = 0.5f * phi.x;
        row[k * 6 + 4] = 0.5f * phi.y;
        row[k * 6 + 5] = 0.5f * phi.z;
    }

    // ---- base residuals: warp 0, one element per lane (warp-uniform branch) ----
    if (t < EPB) {
        const float* b2 = s + S_BASE + t * 7;
        V rho, phi;
        pose_err_log(s + S_DB, V{b2[0], b2[1], b2[2]},
                     Q{b2[3], b2[4], b2[5], b2[6]}, rho, phi);
        float* r2 = s + S_OUT + t * OUTC;
        r2[88] = rho.x * 5.0f;
        r2[89] = rho.y * 5.0f;
        r2[90] = rho.z * 5.0f;
        r2[91] = phi.x * 5.0f;
        r2[92] = phi.y * 5.0f;
        r2[93] = phi.z * 5.0f;
    }

    __syncthreads();

    // ---- flat vectorized flush: EPB*OUTC floats = 752 float4 ----
    {
        float4* go4 = (float4*)(out + (size_t)e0 * OUTC);
        const float4* s4 = (const float4*)(s + S_OUT);
        #pragma unroll
        for (int f = t; f < EPB * OUTC / 4; f += TPB) go4[f] = s4[f];
    }
}

extern "C" void kernel_launch(void* const* d_in, const int* in_sizes, int n_in,
                              void* d_out, int out_size) {
    const float* cfg   = (const float*)d_in[0];
    const float* base  = (const float*)d_in[1];
    const float* tgt   = (const float*)d_in[2];
    const float* dbase = (const float*)d_in[3];
    const float* rest  = (const float*)d_in[4];
    const float* joff  = (const float*)d_in[5];
    const float* jaxis = (const float*)d_in[6];
    const float* jlo   = (const float*)d_in[7];
    const float* jup   = (const float*)d_in[8];
    float* out = (float*)d_out;

    const int smem_bytes = S_TOTAL * sizeof(float);   // 14860
    cudaFuncSetAttribute(ik_residual_kernel,
                         cudaFuncAttributeMaxDynamicSharedMemorySize, smem_bytes);

    int B = in_sizes[0] / NJ;     // 65536
    int nblocks = B / EPB;        // 2048

    ik_residual_kernel<<<nblocks, TPB, smem_bytes>>>(cfg, base, tgt, dbase, rest,
                                                     joff, jaxis, jlo, jup, out);
}

// round 9
// speedup vs baseline: 1.0998x; 1.0998x over previous
#include <cuda_runtime.h>

#define NJ   32
#define TPB  64
#define OUTC 94

// ---- dynamic smem float offsets ----
#define S_OUT   0                       // TPB*OUTC = 6016 floats (also cfg-stage scratch)
#define S_BASE  (TPB * OUTC)            // 6016  (TPB x 8, padded)
#define S_TGT   (S_BASE + TPB * 8)      // 6528  (4 x 8, padded)
#define S_DB    (S_TGT + 32)            // 6560  (8, padded)
#define S_REC   (S_DB + 8)              // 6568  (32 x 16 joint records)
#define S_TOTAL (S_REC + 512)           // 7080 floats = 28320 B

#define CFG_PAD 36                      // padded cfg row stride in staging scratch

struct Q { float x, y, z, w; };
struct V { float x, y, z; };

__device__ __forceinline__ V vcross(V a, V b) {
    return {a.y * b.z - a.z * b.y,
            a.z * b.x - a.x * b.z,
            a.x * b.y - a.y * b.x};
}

__device__ __forceinline__ V qrot(Q q, V t) {
    V v{q.x, q.y, q.z};
    V u = vcross(v, t);
    u.x = fmaf(q.w, t.x, u.x);
    u.y = fmaf(q.w, t.y, u.y);
    u.z = fmaf(q.w, t.z, u.z);
    V c = vcross(v, u);
    return {fmaf(2.0f, c.x, t.x), fmaf(2.0f, c.y, t.y), fmaf(2.0f, c.z, t.z)};
}

__device__ __forceinline__ Q qmul(Q a, Q b) {
    Q r;
    r.w = a.w * b.w - a.x * b.x - a.y * b.y - a.z * b.z;
    r.x = a.w * b.x + b.w * a.x + a.y * b.z - a.z * b.y;
    r.y = a.w * b.y + b.w * a.y + a.z * b.x - a.x * b.z;
    r.z = a.w * b.z + b.w * a.z + a.x * b.y - a.y * b.x;
    return r;
}

// (t1,q1) <- (t1,q1) o (t2,q2)
__device__ __forceinline__ void se3_acc(V& t1, Q& q1, V t2, Q q2) {
    V r = qrot(q1, t2);
    t1.x += r.x; t1.y += r.y; t1.z += r.z;
    q1 = qmul(q1, q2);
}

// atan2(y,x), y >= 0, x >= 0, not both zero
__device__ __forceinline__ float atan2pos(float y, float x) {
    float mn = fminf(y, x), mx = fmaxf(y, x);
    float r  = __fdividef(mn, mx);
    float r2 = r * r;
    float p = fmaf(r2, -0.0117212f,  0.05265332f);
    p = fmaf(r2, p, -0.11643287f);
    p = fmaf(r2, p,  0.19354346f);
    p = fmaf(r2, p, -0.33262347f);
    p = fmaf(r2, p,  0.99997726f);
    float th = r * p;
    return (y > x) ? (1.57079632679489662f - th) : th;
}

// se3_log for unit quaternion (trig-free tail)
__device__ __forceinline__ void se3_log(V t, Q q, V& rho, V& phi) {
    float sgn = (q.w < 0.0f) ? -1.0f : 1.0f;
    float qx = q.x * sgn, qy = q.y * sgn, qz = q.z * sgn, qw = q.w * sgn;
    float nv2 = qx * qx + qy * qy + qz * qz;
    float nv  = sqrtf(fmaxf(nv2, 1e-14f));
    float angle = 2.0f * atan2pos(nv, qw);
    float wsafe = (fabsf(qw) > 1e-8f) ? qw : 1.0f;
    float scale = (nv < 1e-6f) ? __fdividef(2.0f, wsafe) : __fdividef(angle, nv);
    phi = {qx * scale, qy * scale, qz * scale};

    float th2 = angle * angle;
    float abig = __fdividef(1.0f - 0.5f * scale * qw, th2);
    float a = (angle < 1e-4f) ? (1.0f / 12.0f + th2 * (1.0f / 720.0f)) : abig;

    V pt  = vcross(phi, t);
    V ppt = vcross(phi, pt);
    rho = {t.x - 0.5f * pt.x + a * ppt.x,
           t.y - 0.5f * pt.y + a * ppt.y,
           t.z - 0.5f * pt.z + a * ppt.z};
}

// log( inv(target) o actual ); target padded to 8 floats: [t(3),pad | q(4)]
__device__ __forceinline__ void pose_err_log(const float* tp, V at, Q aq,
                                             V& rho, V& phi) {
    float4 a = *(const float4*)tp;
    float4 b = *(const float4*)(tp + 4);
    Q qi{-b.x, -b.y, -b.z, b.w};
    V d{at.x - a.x, at.y - a.y, at.z - a.z};
    V pe = qrot(qi, d);
    Q qe = qmul(qi, aq);
    se3_log(pe, qe, rho, phi);
}

__global__ void __launch_bounds__(TPB, 8)
ik_residual_kernel(const float* __restrict__ cfg,
                   const float* __restrict__ base,
                   const float* __restrict__ tgt,
                   const float* __restrict__ dbase,
                   const float* __restrict__ rest,
                   const float* __restrict__ joff,
                   const float* __restrict__ jaxis,
                   const float* __restrict__ jlo,
                   const float* __restrict__ jup,
                   float* __restrict__ out) {
    extern __shared__ __align__(16) float s[];

    const int t  = threadIdx.x;
    const int b0 = blockIdx.x * TPB;

    // ---- stage: base (padded 8), cfg tile (-> S_OUT scratch), joint records ----
    {
        const float* gb = base + (size_t)b0 * 7;
        #pragma unroll
        for (int i = t; i < TPB * 7; i += TPB) {
            int r = i / 7, c = i - r * 7;
            s[S_BASE + r * 8 + c] = gb[i];
        }

        const float4* gc = (const float4*)(cfg + (size_t)b0 * NJ);
        #pragma unroll
        for (int f = t; f < TPB * (NJ / 4); f += TPB) {
            int r = f >> 3;
            int c = f & 7;
            *(float4*)(s + S_OUT + r * CFG_PAD + c * 4) = __ldg(gc + f);
        }

        if (t < 32) {
            // joint record: [ot.xyz, rest | oq.xyzw | P.xyzw | up, lo, 0, 0]
            float otx = __ldg(joff + t * 7 + 0), oty = __ldg(joff + t * 7 + 1);
            float otz = __ldg(joff + t * 7 + 2);
            float ox = __ldg(joff + t * 7 + 3), oy = __ldg(joff + t * 7 + 4);
            float oz = __ldg(joff + t * 7 + 5), ow = __ldg(joff + t * 7 + 6);
            float ax = __ldg(jaxis + t * 3 + 0), ay = __ldg(jaxis + t * 3 + 1);
            float az = __ldg(jaxis + t * 3 + 2);
            float4* R = (float4*)(s + S_REC) + t * 4;
            R[0] = make_float4(otx, oty, otz, __ldg(rest + t));
            R[1] = make_float4(ox, oy, oz, ow);
            R[2] = make_float4(ow * ax + oy * az - oz * ay,
                               ow * ay + oz * ax - ox * az,
                               ow * az + ox * ay - oy * ax,
                               -(ox * ax + oy * ay + oz * az));
            R[3] = make_float4(__ldg(jup + t), __ldg(jlo + t), 0.0f, 0.0f);
        }
        if (t < 5) {
            const float* src = (t < 4) ? (tgt + t * 7) : dbase;
            float* dst = s + ((t < 4) ? (S_TGT + t * 8) : S_DB);
            dst[0] = __ldg(src + 0); dst[1] = __ldg(src + 1);
            dst[2] = __ldg(src + 2); dst[3] = 0.0f;
            dst[4] = __ldg(src + 3); dst[5] = __ldg(src + 4);
            dst[6] = __ldg(src + 5); dst[7] = __ldg(src + 6);
        }
    }
    __syncthreads();

    // own base pose + cfg row from smem
    float bp[7];
    {
        float4 b1 = *(const float4*)(s + S_BASE + t * 8);
        float4 b2 = *(const float4*)(s + S_BASE + t * 8 + 4);
        bp[0] = b1.x; bp[1] = b1.y; bp[2] = b1.z; bp[3] = b1.w;
        bp[4] = b2.x; bp[5] = b2.y; bp[6] = b2.z;
    }
    float th[NJ];
    {
        const float4* cr = (const float4*)(s + S_OUT + t * CFG_PAD);
        #pragma unroll
        for (int i = 0; i < NJ / 4; i++) {
            float4 v = cr[i];
            th[4*i+0] = v.x; th[4*i+1] = v.y; th[4*i+2] = v.z; th[4*i+3] = v.w;
        }
    }
    __syncthreads();   // cfg scratch becomes output staging

    float* row = s + S_OUT + t * OUTC;   // (t*94*4 bytes: 8B-aligned -> float2 stores ok)

    V Tt{bp[0], bp[1], bp[2]};
    Q Tq{bp[3], bp[4], bp[5], bp[6]};

    const float4* REC = (const float4*)(s + S_REC);

    // ---- tree-structured FK: 4 segments of 8 joints ----
    #pragma unroll
    for (int seg = 0; seg < 4; seg++) {
        const int j0 = seg * 8;

        // leaves: M_j = ch*oq + sh*P; T_j = ot; limit/rest residuals (float2 stores)
        Q M[8];
        V T[8];
        #pragma unroll
        for (int i = 0; i < 8; i += 2) {
            float l0, l1, r0v, r1v;
            #pragma unroll
            for (int u = 0; u < 2; u++) {
                const int ii = i + u;
                const int j = j0 + ii;
                const float4* R = REC + j * 4;
                float4 a0 = R[0];     // ot, rest
                float4 a1 = R[1];     // oq
                float4 a2 = R[2];     // P
                float4 a3 = R[3];     // up, lo
                float thj = th[j];
                float lim = fmaxf(thj - a3.x, 0.0f) + fminf(thj - a3.y, 0.0f);
                float rst = (thj - a0.w) * 0.1f;
                if (u == 0) { l0 = lim * 10.0f; r0v = rst; }
                else        { l1 = lim * 10.0f; r1v = rst; }

                float sh, ch;
                __sincosf(0.5f * thj, &sh, &ch);
                M[ii].x = fmaf(sh, a2.x, ch * a1.x);
                M[ii].y = fmaf(sh, a2.y, ch * a1.y);
                M[ii].z = fmaf(sh, a2.z, ch * a1.z);
                M[ii].w = fmaf(sh, a2.w, ch * a1.w);
                T[ii].x = a0.x; T[ii].y = a0.y; T[ii].z = a0.z;
            }
            *(float2*)(row + 24 + j0 + i) = make_float2(l0, l1);
            *(float2*)(row + 56 + j0 + i) = make_float2(r0v, r1v);
        }

        // level 1: 4 independent composes
        V t01 = T[0]; Q q01 = M[0]; se3_acc(t01, q01, T[1], M[1]);
        V t23 = T[2]; Q q23 = M[2]; se3_acc(t23, q23, T[3], M[3]);
        V t45 = T[4]; Q q45 = M[4]; se3_acc(t45, q45, T[5], M[5]);
        V t67 = T[6]; Q q67 = M[6]; se3_acc(t67, q67, T[7], M[7]);

        // level 2 + 3
        se3_acc(t01, q01, t23, q23);
        se3_acc(t45, q45, t67, q67);
        se3_acc(t01, q01, t45, q45);

        // chain into running pose (prefix at target link)
        se3_acc(Tt, Tq, t01, q01);

        V rho, phi;
        pose_err_log(s + S_TGT + seg * 8, Tt, Tq, rho, phi);
        *(float2*)(row + seg * 6 + 0) = make_float2(rho.x, rho.y);
        *(float2*)(row + seg * 6 + 2) = make_float2(rho.z, 0.5f * phi.x);
        *(float2*)(row + seg * 6 + 4) = make_float2(0.5f * phi.y, 0.5f * phi.z);
    }

    // ---- base residual ----
    {
        V rho, phi;
        pose_err_log(s + S_DB, V{bp[0], bp[1], bp[2]},
                     Q{bp[3], bp[4], bp[5], bp[6]}, rho, phi);
        *(float2*)(row + 88) = make_float2(rho.x * 5.0f, rho.y * 5.0f);
        *(float2*)(row + 90) = make_float2(rho.z * 5.0f, phi.x * 5.0f);
        *(float2*)(row + 92) = make_float2(phi.y * 5.0f, phi.z * 5.0f);
    }

    __syncthreads();

    // ---- flat vectorized flush: TPB*OUTC floats = 1504 float4 ----
    {
        float4* go4 = (float4*)(out + (size_t)b0 * OUTC);
        const float4* s4 = (const float4*)(s + S_OUT);
        #pragma unroll
        for (int f = t; f < TPB * OUTC / 4; f += TPB) go4[f] = s4[f];
    }
}

extern "C" void kernel_launch(void* const* d_in, const int* in_sizes, int n_in,
                              void* d_out, int out_size) {
    const float* cfg   = (const float*)d_in[0];
    const float* base  = (const float*)d_in[1];
    const float* tgt   = (const float*)d_in[2];
    const float* dbase = (const float*)d_in[3];
    const float* rest  = (const float*)d_in[4];
    const float* joff  = (const float*)d_in[5];
    const float* jaxis = (const float*)d_in[6];
    const float* jlo   = (const float*)d_in[7];
    const float* jup   = (const float*)d_in[8];
    float* out = (float*)d_out;

    const int smem_bytes = S_TOTAL * sizeof(float);   // 28320
    cudaFuncSetAttribute(ik_residual_kernel,
                         cudaFuncAttributeMaxDynamicSharedMemorySize, smem_bytes);

    int B = in_sizes[0] / NJ;     // 65536
    int nblocks = B / TPB;        // 1024

    ik_residual_kernel<<<nblocks, TPB, smem_bytes>>>(cfg, base, tgt, dbase, rest,
                                                     joff, jaxis, jlo, jup, out);
}

// round 10
// speedup vs baseline: 1.1021x; 1.0021x over previous
#include <cuda_runtime.h>

#define NJ   32
#define TPB  128
#define EPB  (TPB / 2)     // 64 elements per block, 2 threads each
#define OUTC 94

// ---- dynamic smem float offsets ----
#define S_OUT   0                       // EPB*OUTC = 6016 floats (also cfg-stage scratch)
#define S_BASE  (EPB * OUTC)            // 6016  (EPB x 8, padded)
#define S_TGT   (S_BASE + EPB * 8)      // 6528  (4 x 8, padded)
#define S_DB    (S_TGT + 32)            // 6560  (8)
#define S_REC   (S_DB + 8)              // 6568  (32 x 16 joint records)
#define S_TOTAL (S_REC + 512)           // 7080 floats = 28320 B

#define CFG_PAD 36                      // padded cfg row stride in staging scratch

struct Q { float x, y, z, w; };
struct V { float x, y, z; };

__device__ __forceinline__ V vcross(V a, V b) {
    return {a.y * b.z - a.z * b.y,
            a.z * b.x - a.x * b.z,
            a.x * b.y - a.y * b.x};
}

__device__ __forceinline__ V qrot(Q q, V t) {
    V v{q.x, q.y, q.z};
    V u = vcross(v, t);
    u.x = fmaf(q.w, t.x, u.x);
    u.y = fmaf(q.w, t.y, u.y);
    u.z = fmaf(q.w, t.z, u.z);
    V c = vcross(v, u);
    return {fmaf(2.0f, c.x, t.x), fmaf(2.0f, c.y, t.y), fmaf(2.0f, c.z, t.z)};
}

__device__ __forceinline__ Q qmul(Q a, Q b) {
    Q r;
    r.w = a.w * b.w - a.x * b.x - a.y * b.y - a.z * b.z;
    r.x = a.w * b.x + b.w * a.x + a.y * b.z - a.z * b.y;
    r.y = a.w * b.y + b.w * a.y + a.z * b.x - a.x * b.z;
    r.z = a.w * b.z + b.w * a.z + a.x * b.y - a.y * b.x;
    return r;
}

// (t1,q1) <- (t1,q1) o (t2,q2)
__device__ __forceinline__ void se3_acc(V& t1, Q& q1, V t2, Q q2) {
    V r = qrot(q1, t2);
    t1.x += r.x; t1.y += r.y; t1.z += r.z;
    q1 = qmul(q1, q2);
}

// out = (t1,q1) o (t2,q2)
__device__ __forceinline__ void se3_comp(V t1, Q q1, V t2, Q q2, V& to, Q& qo) {
    V r = qrot(q1, t2);
    to.x = t1.x + r.x; to.y = t1.y + r.y; to.z = t1.z + r.z;
    qo = qmul(q1, q2);
}

// atan2(y,x), y >= 0, x >= 0, not both zero
__device__ __forceinline__ float atan2pos(float y, float x) {
    float mn = fminf(y, x), mx = fmaxf(y, x);
    float r  = __fdividef(mn, mx);
    float r2 = r * r;
    float p = fmaf(r2, -0.0117212f,  0.05265332f);
    p = fmaf(r2, p, -0.11643287f);
    p = fmaf(r2, p,  0.19354346f);
    p = fmaf(r2, p, -0.33262347f);
    p = fmaf(r2, p,  0.99997726f);
    float th = r * p;
    return (y > x) ? (1.57079632679489662f - th) : th;
}

// se3_log for unit quaternion (trig-free tail)
__device__ __forceinline__ void se3_log(V t, Q q, V& rho, V& phi) {
    float sgn = (q.w < 0.0f) ? -1.0f : 1.0f;
    float qx = q.x * sgn, qy = q.y * sgn, qz = q.z * sgn, qw = q.w * sgn;
    float nv2 = qx * qx + qy * qy + qz * qz;
    float nv  = sqrtf(fmaxf(nv2, 1e-14f));
    float angle = 2.0f * atan2pos(nv, qw);
    float wsafe = (fabsf(qw) > 1e-8f) ? qw : 1.0f;
    float scale = (nv < 1e-6f) ? __fdividef(2.0f, wsafe) : __fdividef(angle, nv);
    phi = {qx * scale, qy * scale, qz * scale};

    float th2 = angle * angle;
    float abig = __fdividef(1.0f - 0.5f * scale * qw, th2);
    float a = (angle < 1e-4f) ? (1.0f / 12.0f + th2 * (1.0f / 720.0f)) : abig;

    V pt  = vcross(phi, t);
    V ppt = vcross(phi, pt);
    rho = {t.x - 0.5f * pt.x + a * ppt.x,
           t.y - 0.5f * pt.y + a * ppt.y,
           t.z - 0.5f * pt.z + a * ppt.z};
}

// log( inv(target) o actual ); target padded to 8 floats: [t(3),pad | q(4)]
__device__ __forceinline__ void pose_err_log(const float* tp, V at, Q aq,
                                             V& rho, V& phi) {
    float4 a = *(const float4*)tp;
    float4 b = *(const float4*)(tp + 4);
    Q qi{-b.x, -b.y, -b.z, b.w};
    V d{at.x - a.x, at.y - a.y, at.z - a.z};
    V pe = qrot(qi, d);
    Q qe = qmul(qi, aq);
    se3_log(pe, qe, rho, phi);
}

// product of X_{j0}..X_{j0+7} via pairwise tree, with limit/rest residual stores
__device__ __forceinline__ void prod8(const float4* REC, int j0, const float* th8,
                                      float* row, V& St, Q& Sq) {
    Q M[8];
    V T[8];
    #pragma unroll
    for (int i = 0; i < 8; i += 2) {
        float l0, l1, r0v, r1v;
        #pragma unroll
        for (int u = 0; u < 2; u++) {
            const int ii = i + u;
            const float4* R = REC + (j0 + ii) * 4;
            float4 a0 = R[0];     // ot, rest
            float4 a1 = R[1];     // oq
            float4 a2 = R[2];     // P
            float4 a3 = R[3];     // up, lo
            float thj = th8[ii];
            float lim = fmaxf(thj - a3.x, 0.0f) + fminf(thj - a3.y, 0.0f);
            float rst = (thj - a0.w) * 0.1f;
            if (u == 0) { l0 = lim * 10.0f; r0v = rst; }
            else        { l1 = lim * 10.0f; r1v = rst; }

            float sh, ch;
            __sincosf(0.5f * thj, &sh, &ch);
            M[ii].x = fmaf(sh, a2.x, ch * a1.x);
            M[ii].y = fmaf(sh, a2.y, ch * a1.y);
            M[ii].z = fmaf(sh, a2.z, ch * a1.z);
            M[ii].w = fmaf(sh, a2.w, ch * a1.w);
            T[ii].x = a0.x; T[ii].y = a0.y; T[ii].z = a0.z;
        }
        *(float2*)(row + 24 + j0 + i) = make_float2(l0, l1);
        *(float2*)(row + 56 + j0 + i) = make_float2(r0v, r1v);
    }

    V t01 = T[0]; Q q01 = M[0]; se3_acc(t01, q01, T[1], M[1]);
    V t23 = T[2]; Q q23 = M[2]; se3_acc(t23, q23, T[3], M[3]);
    V t45 = T[4]; Q q45 = M[4]; se3_acc(t45, q45, T[5], M[5]);
    V t67 = T[6]; Q q67 = M[6]; se3_acc(t67, q67, T[7], M[7]);

    se3_acc(t01, q01, t23, q23);
    se3_acc(t45, q45, t67, q67);
    se3_acc(t01, q01, t45, q45);
    St = t01; Sq = q01;
}

__global__ void __launch_bounds__(TPB, 7)
ik_residual_kernel(const float* __restrict__ cfg,
                   const float* __restrict__ base,
                   const float* __restrict__ tgt,
                   const float* __restrict__ dbase,
                   const float* __restrict__ rest,
                   const float* __restrict__ joff,
                   const float* __restrict__ jaxis,
                   const float* __restrict__ jlo,
                   const float* __restrict__ jup,
                   float* __restrict__ out) {
    extern __shared__ __align__(16) float s[];

    const int t    = threadIdx.x;
    const int elem = t >> 1;        // 0..63
    const int seg  = t & 1;         // 0 -> joints 0-15, 1 -> joints 16-31
    const int e0   = blockIdx.x * EPB;

    // ---- stage: base (padded 8), cfg tile (-> S_OUT scratch), records, targets ----
    {
        const float* gb = base + (size_t)e0 * 7;
        #pragma unroll
        for (int i = t; i < EPB * 7; i += TPB) {
            int r = i / 7, c = i - r * 7;
            s[S_BASE + r * 8 + c] = gb[i];
        }

        const float4* gc = (const float4*)(cfg + (size_t)e0 * NJ);
        #pragma unroll
        for (int f = t; f < EPB * (NJ / 4); f += TPB) {
            int r = f >> 3;
            int c = f & 7;
            *(float4*)(s + S_OUT + r * CFG_PAD + c * 4) = __ldg(gc + f);
        }

        if (t < 32) {
            float otx = __ldg(joff + t * 7 + 0), oty = __ldg(joff + t * 7 + 1);
            float otz = __ldg(joff + t * 7 + 2);
            float ox = __ldg(joff + t * 7 + 3), oy = __ldg(joff + t * 7 + 4);
            float oz = __ldg(joff + t * 7 + 5), ow = __ldg(joff + t * 7 + 6);
            float ax = __ldg(jaxis + t * 3 + 0), ay = __ldg(jaxis + t * 3 + 1);
            float az = __ldg(jaxis + t * 3 + 2);
            float4* R = (float4*)(s + S_REC) + t * 4;
            R[0] = make_float4(otx, oty, otz, __ldg(rest + t));
            R[1] = make_float4(ox, oy, oz, ow);
            R[2] = make_float4(ow * ax + oy * az - oz * ay,
                               ow * ay + oz * ax - ox * az,
                               ow * az + ox * ay - oy * ax,
                               -(ox * ax + oy * ay + oz * az));
            R[3] = make_float4(__ldg(jup + t), __ldg(jlo + t), 0.0f, 0.0f);
        }
        if (t < 5) {
            const float* src = (t < 4) ? (tgt + t * 7) : dbase;
            float* dst = s + ((t < 4) ? (S_TGT + t * 8) : S_DB);
            dst[0] = __ldg(src + 0); dst[1] = __ldg(src + 1);
            dst[2] = __ldg(src + 2); dst[3] = 0.0f;
            dst[4] = __ldg(src + 3); dst[5] = __ldg(src + 4);
            dst[6] = __ldg(src + 5); dst[7] = __ldg(src + 6);
        }
    }
    __syncthreads();

    // own half of cfg row + base pose
    float th[16];
    {
        const float4* cr = (const float4*)(s + S_OUT + elem * CFG_PAD + seg * 16);
        #pragma unroll
        for (int i = 0; i < 4; i++) {
            float4 v = cr[i];
            th[4*i+0] = v.x; th[4*i+1] = v.y; th[4*i+2] = v.z; th[4*i+3] = v.w;
        }
    }
    float bp[7];
    {
        float4 b1 = *(const float4*)(s + S_BASE + elem * 8);
        float4 b2 = *(const float4*)(s + S_BASE + elem * 8 + 4);
        bp[0] = b1.x; bp[1] = b1.y; bp[2] = b1.z; bp[3] = b1.w;
        bp[4] = b2.x; bp[5] = b2.y; bp[6] = b2.z;
    }
    __syncthreads();   // cfg scratch becomes output staging

    float* row = s + S_OUT + elem * OUTC;
    const float4* REC = (const float4*)(s + S_REC);
    const int j0 = seg * 16;

    // ---- two 8-joint products + 16-joint product ----
    V S1t, S2t, Et; Q S1q, S2q, Eq;
    prod8(REC, j0,     th,     row, S1t, S1q);
    prod8(REC, j0 + 8, th + 8, row, S2t, S2q);
    se3_comp(S1t, S1q, S2t, S2q, Et, Eq);      // E = 16-joint product

    // ---- G = base o E (lane0 of pair: T16) ----
    V bt{bp[0], bp[1], bp[2]};
    Q bq{bp[3], bp[4], bp[5], bp[6]};
    V Gt; Q Gq;
    se3_comp(bt, bq, Et, Eq, Gt, Gq);

    // broadcast lane0's G (=T16) within the pair
    V Lt; Q Lq;
    Lt.x = __shfl_sync(0xffffffffu, Gt.x, 0, 2);
    Lt.y = __shfl_sync(0xffffffffu, Gt.y, 0, 2);
    Lt.z = __shfl_sync(0xffffffffu, Gt.z, 0, 2);
    Lq.x = __shfl_sync(0xffffffffu, Gq.x, 0, 2);
    Lq.y = __shfl_sync(0xffffffffu, Gq.y, 0, 2);
    Lq.z = __shfl_sync(0xffffffffu, Gq.z, 0, 2);
    Lq.w = __shfl_sync(0xffffffffu, Gq.w, 0, 2);

    // prefix select: seg0 -> base, seg1 -> T16
    V Pt; Q Pq;
    Pt.x = seg ? Lt.x : bt.x;  Pt.y = seg ? Lt.y : bt.y;  Pt.z = seg ? Lt.z : bt.z;
    Pq.x = seg ? Lq.x : bq.x;  Pq.y = seg ? Lq.y : bq.y;
    Pq.z = seg ? Lq.z : bq.z;  Pq.w = seg ? Lq.w : bq.w;

    // U1 = P o S1 (T8 / T24), U2 = P o E (T16 / T32) -- independent
    V U1t, U2t; Q U1q, U2q;
    se3_comp(Pt, Pq, S1t, S1q, U1t, U1q);
    se3_comp(Pt, Pq, Et,  Eq,  U2t, U2q);

    // ---- pose residuals (2 per thread) ----
    {
        V rho, phi;
        int k = seg * 2;
        pose_err_log(s + S_TGT + k * 8, U1t, U1q, rho, phi);
        *(float2*)(row + k * 6 + 0) = make_float2(rho.x, rho.y);
        *(float2*)(row + k * 6 + 2) = make_float2(rho.z, 0.5f * phi.x);
        *(float2*)(row + k * 6 + 4) = make_float2(0.5f * phi.y, 0.5f * phi.z);

        k = seg * 2 + 1;
        pose_err_log(s + S_TGT + k * 8, U2t, U2q, rho, phi);
        *(float2*)(row + k * 6 + 0) = make_float2(rho.x, rho.y);
        *(float2*)(row + k * 6 + 2) = make_float2(rho.z, 0.5f * phi.x);
        *(float2*)(row + k * 6 + 4) = make_float2(0.5f * phi.y, 0.5f * phi.z);
    }

    // ---- base residuals: all 4 warps, lanes 0-15, one element each (balanced) ----
    {
        const int lane = t & 31;
        const int w    = t >> 5;
        if (lane < 16) {
            const int el = w * 16 + lane;   // 0..63
            float4 b1 = *(const float4*)(s + S_BASE + el * 8);
            float4 b2 = *(const float4*)(s + S_BASE + el * 8 + 4);
            V rho, phi;
            pose_err_log(s + S_DB, V{b1.x, b1.y, b1.z},
                         Q{b1.w, b2.x, b2.y, b2.z}, rho, phi);
            float* r2 = s + S_OUT + el * OUTC;
            *(float2*)(r2 + 88) = make_float2(rho.x * 5.0f, rho.y * 5.0f);
            *(float2*)(r2 + 90) = make_float2(rho.z * 5.0f, phi.x * 5.0f);
            *(float2*)(r2 + 92) = make_float2(phi.y * 5.0f, phi.z * 5.0f);
        }
    }

    __syncthreads();

    // ---- flat vectorized flush: EPB*OUTC floats = 1504 float4 ----
    {
        float4* go4 = (float4*)(out + (size_t)e0 * OUTC);
        const float4* s4 = (const float4*)(s + S_OUT);
        #pragma unroll
        for (int f = t; f < EPB * OUTC / 4; f += TPB) go4[f] = s4[f];
    }
}

extern "C" void kernel_launch(void* const* d_in, const int* in_sizes, int n_in,
                              void* d_out, int out_size) {
    const float* cfg   = (const float*)d_in[0];
    const float* base  = (const float*)d_in[1];
    const float* tgt   = (const float*)d_in[2];
    const float* dbase = (const float*)d_in[3];
    const float* rest  = (const float*)d_in[4];
    const float* joff  = (const float*)d_in[5];
    const float* jaxis = (const float*)d_in[6];
    const float* jlo   = (const float*)d_in[7];
    const float* jup   = (const float*)d_in[8];
    float* out = (float*)d_out;

    const int smem_bytes = S_TOTAL * sizeof(float);   // 28320
    cudaFuncSetAttribute(ik_residual_kernel,
                         cudaFuncAttributeMaxDynamicSharedMemorySize, smem_bytes);

    int B = in_sizes[0] / NJ;     // 65536
    int nblocks = B / EPB;        // 1024

    ik_residual_kernel<<<nblocks, TPB, smem_bytes>>>(cfg, base, tgt, dbase, rest,
                                                     joff, jaxis, jlo, jup, out);
}